// round 14
// baseline (speedup 1.0000x reference)
#include <cuda_runtime.h>
#include <cuda_bf16.h>
#include <cuda_fp16.h>
#include <cstdint>

// Problem constants (reference: N=100000, E=1600000, IN=HID=128, OUT=64)
#define NMAX 100000
#define FIN  128
#define FHID 128
#define FOUT 64

// ---------------------------------------------------------------------------
// Device-global scratch (no allocation allowed)
// ---------------------------------------------------------------------------
__device__ int      g_deg[NMAX];
__device__ int      g_off[NMAX];               // segment start per node
__device__ int      g_cursor[NMAX];
__device__ int      g_total;                   // single-pass scan base counter
__device__ float    g_dinv[NMAX];
__device__ int      g_eidx[1600000];
__device__ __half   g_Hsh [(size_t)NMAX * FHID]; // X@W1 (UNSCALED), fp16 messages
__device__ __half   g_Hs2h[(size_t)NMAX * FOUT]; // (H2@W2)*dinv[row], fp16 messages
// packed split weights: [n][pair] with pair = k/2
__device__ uint32_t g_W1h[128 * 64], g_W1l[128 * 64];
__device__ uint32_t g_W2h[64 * 64],  g_W2l[64 * 64];

// ---------------------------------------------------------------------------
// Helpers
// ---------------------------------------------------------------------------
__device__ __forceinline__ void split_pack(float f0, float f1, uint32_t& hi, uint32_t& lo) {
    __nv_bfloat16 h0 = __float2bfloat16_rn(f0);
    __nv_bfloat16 h1 = __float2bfloat16_rn(f1);
    __nv_bfloat16 l0 = __float2bfloat16_rn(f0 - __bfloat162float(h0));
    __nv_bfloat16 l1 = __float2bfloat16_rn(f1 - __bfloat162float(h1));
    hi = (uint32_t)__bfloat16_as_ushort(h0) | ((uint32_t)__bfloat16_as_ushort(h1) << 16);
    lo = (uint32_t)__bfloat16_as_ushort(l0) | ((uint32_t)__bfloat16_as_ushort(l1) << 16);
}

// m16n8k16 bf16 MMA, D += A*B (D==C in-place)
__device__ __forceinline__ void mma16816(float* d, const uint32_t* a, const uint32_t* b) {
    asm volatile(
        "mma.sync.aligned.m16n8k16.row.col.f32.bf16.bf16.f32 "
        "{%0,%1,%2,%3}, {%4,%5,%6,%7}, {%8,%9}, {%0,%1,%2,%3};"
        : "+f"(d[0]), "+f"(d[1]), "+f"(d[2]), "+f"(d[3])
        : "r"(a[0]), "r"(a[1]), "r"(a[2]), "r"(a[3]), "r"(b[0]), "r"(b[1]));
}

#define PSTR 20   // per-chunk tile stride (gemm1)
#define FSTR 68   // full-K tile stride (fused kernel): (4r+c) mod 32 bijective

// ---------------------------------------------------------------------------
// k_prep: zero deg + total, pack W1/W2 into bf16 hi/lo pairs. One kernel.
// ---------------------------------------------------------------------------
__global__ void k_prep(const float* __restrict__ W1, const float* __restrict__ W2, int N) {
    int i = blockIdx.x * blockDim.x + threadIdx.x;
    if (i < N) g_deg[i] = 0;
    if (i == 0) g_total = 0;
    if (i < 128 * 64) {
        int n = i >> 6, p = (i & 63) * 2;
        uint32_t h, l;
        split_pack(W1[(size_t)p * FHID + n], W1[(size_t)(p + 1) * FHID + n], h, l);
        g_W1h[i] = h; g_W1l[i] = l;
    } else if (i < 128 * 64 + 64 * 64) {
        int j = i - 128 * 64;
        int n = j >> 6, p = (j & 63) * 2;
        uint32_t h, l;
        split_pack(W2[(size_t)p * FOUT + n], W2[(size_t)(p + 1) * FOUT + n], h, l);
        g_W2h[j] = h; g_W2l[j] = l;
    }
}

__global__ void k_count(const int* __restrict__ col, int E) {
    int e = blockIdx.x * blockDim.x + threadIdx.x;
    if (e < E) atomicAdd(&g_deg[col[e]], 1);
}

// Single-pass scan: per-block scan + atomic global base.
__global__ __launch_bounds__(1024) void k_scan1(int N) {
    __shared__ int s[1024];
    __shared__ int sbase;
    int t = threadIdx.x;
    int i = blockIdx.x * 1024 + t;
    int v = (i < N) ? g_deg[i] : 0;
    s[t] = v;
    __syncthreads();
#pragma unroll
    for (int d = 1; d < 1024; d <<= 1) {
        int x = s[t];
        if (t >= d) x += s[t - d];
        __syncthreads();
        s[t] = x;
        __syncthreads();
    }
    if (t == 1023) sbase = atomicAdd(&g_total, s[1023]);
    __syncthreads();
    if (i < N) {
        int o = sbase + s[t] - v;
        g_off[i]    = o;
        g_cursor[i] = o;
        g_dinv[i]   = rsqrtf((float)v + 1.0f);
    }
}

__global__ void k_place(const int* __restrict__ row, const int* __restrict__ col, int E) {
    int e = blockIdx.x * blockDim.x + threadIdx.x;
    if (e < E) {
        int c = col[e];
        int p = atomicAdd(&g_cursor[c], 1);
        g_eidx[p] = row[e];
    }
}

// ---------------------------------------------------------------------------
// GEMM1 (mma.sync bf16-split): Hsh = fp16(X @ W1)  -- UNSCALED.
// CTA 128x128, 8 warps in 2m x 4n. K in 4 chunks of 32. B from packed weights.
// ---------------------------------------------------------------------------
__global__ __launch_bounds__(256) void k_gemm1(
    const float* __restrict__ X, int N)
{
    __shared__ uint32_t AsH[128 * PSTR], AsL[128 * PSTR];
    __shared__ uint32_t BsH[128 * PSTR], BsL[128 * PSTR];

    const int tid  = threadIdx.x;
    const int lane = tid & 31;
    const int wid  = tid >> 5;
    const int wm   = wid & 1;
    const int wn   = wid >> 1;
    const int bi   = blockIdx.x * 128;

    const int ar  = tid >> 1;
    const int akh = (tid & 1) * 16;
    const int arc = min(bi + ar, N - 1);
    const float* Xrow = X + (size_t)arc * FIN;

    const int bn  = tid >> 1;
    const int bp0 = (tid & 1) * 8;

    float acc[4][4][4];
#pragma unroll
    for (int mi = 0; mi < 4; mi++)
#pragma unroll
        for (int ni = 0; ni < 4; ni++)
#pragma unroll
            for (int q = 0; q < 4; q++) acc[mi][ni][q] = 0.f;

    for (int ch = 0; ch < 4; ch++) {
        const int kc = ch * 32;
        const int cp = ch * 16;
        __syncthreads();
#pragma unroll
        for (int i = 0; i < 4; i++) {
            float4 v = *(const float4*)&Xrow[kc + akh + 4 * i];
            uint32_t h0, l0, h1, l1;
            split_pack(v.x, v.y, h0, l0);
            split_pack(v.z, v.w, h1, l1);
            int p = ar * PSTR + (akh >> 1) + 2 * i;
            AsH[p] = h0; AsH[p + 1] = h1;
            AsL[p] = l0; AsL[p + 1] = l1;
        }
        {
            uint4 h0 = *(const uint4*)&g_W1h[bn * 64 + cp + bp0];
            uint4 h1 = *(const uint4*)&g_W1h[bn * 64 + cp + bp0 + 4];
            uint4 l0 = *(const uint4*)&g_W1l[bn * 64 + cp + bp0];
            uint4 l1 = *(const uint4*)&g_W1l[bn * 64 + cp + bp0 + 4];
            *(uint4*)&BsH[bn * PSTR + bp0]     = h0;
            *(uint4*)&BsH[bn * PSTR + bp0 + 4] = h1;
            *(uint4*)&BsL[bn * PSTR + bp0]     = l0;
            *(uint4*)&BsL[bn * PSTR + bp0 + 4] = l1;
        }
        __syncthreads();

#pragma unroll
        for (int ks = 0; ks < 2; ks++) {
            const int pb = ks * 8;
            uint32_t bh[4][2], bl[4][2], afr[4][4];
#pragma unroll
            for (int ni = 0; ni < 4; ni++) {
                int idx = (wn * 32 + ni * 8 + (lane >> 2)) * PSTR + pb + (lane & 3);
                bh[ni][0] = BsH[idx]; bh[ni][1] = BsH[idx + 4];
                bl[ni][0] = BsL[idx]; bl[ni][1] = BsL[idx + 4];
            }
#pragma unroll
            for (int mi = 0; mi < 4; mi++) {
                int rb = wm * 64 + mi * 16 + (lane >> 2);
                int i0 = rb * PSTR + pb + (lane & 3);
                int i1 = i0 + 8 * PSTR;
                afr[mi][0] = AsH[i0]; afr[mi][1] = AsH[i1];
                afr[mi][2] = AsH[i0 + 4]; afr[mi][3] = AsH[i1 + 4];
            }
#pragma unroll
            for (int mi = 0; mi < 4; mi++)
#pragma unroll
                for (int ni = 0; ni < 4; ni++) {
                    mma16816(acc[mi][ni], afr[mi], bh[ni]);   // hi*hi
                    mma16816(acc[mi][ni], afr[mi], bl[ni]);   // hi*lo
                }
#pragma unroll
            for (int mi = 0; mi < 4; mi++) {
                int rb = wm * 64 + mi * 16 + (lane >> 2);
                int i0 = rb * PSTR + pb + (lane & 3);
                int i1 = i0 + 8 * PSTR;
                afr[mi][0] = AsL[i0]; afr[mi][1] = AsL[i1];
                afr[mi][2] = AsL[i0 + 4]; afr[mi][3] = AsL[i1 + 4];
            }
#pragma unroll
            for (int mi = 0; mi < 4; mi++)
#pragma unroll
                for (int ni = 0; ni < 4; ni++)
                    mma16816(acc[mi][ni], afr[mi], bh[ni]);   // lo*hi
        }
    }

#pragma unroll
    for (int mi = 0; mi < 4; mi++) {
        int r0 = bi + wm * 64 + mi * 16 + (lane >> 2);
        int r1 = r0 + 8;
#pragma unroll
        for (int ni = 0; ni < 4; ni++) {
            int c = wn * 32 + ni * 8 + (lane & 3) * 2;
            if (r0 < N) {
                __half2 v = __floats2half2_rn(acc[mi][ni][0], acc[mi][ni][1]);
                *(__half2*)&g_Hsh[(size_t)r0 * FHID + c] = v;
            }
            if (r1 < N) {
                __half2 v = __floats2half2_rn(acc[mi][ni][2], acc[mi][ni][3]);
                *(__half2*)&g_Hsh[(size_t)r1 * FHID + c] = v;
            }
        }
    }
}

// ---------------------------------------------------------------------------
// Fused Agg1 + GEMM2. 512 threads, CTA owns 128 nodes.
// Phase A: load full-K B tile (packed W2) into smem.
// Phase B: 16 warps aggregate 8 nodes each (fp16 gather, per-edge dinv, MLP=4);
//          relu(dinv*acc+b1) written DIRECTLY into split-bf16 A tiles in smem.
// Phase C: full-K MMA (no syncs); epilogue scales by dinv and stores fp16 Hs2h.
// Dynamic smem: A 2*128*FSTR + B 2*64*FSTR u32 = 104448 bytes.
// ---------------------------------------------------------------------------
__global__ __launch_bounds__(512) void k_agg1gemm2(const float* __restrict__ b1, int N)
{
    extern __shared__ uint32_t sm[];
    uint32_t* AsH = sm;
    uint32_t* AsL = AsH + 128 * FSTR;
    uint32_t* BsH = AsL + 128 * FSTR;
    uint32_t* BsL = BsH + 64 * FSTR;

    const int tid  = threadIdx.x;
    const int lane = tid & 31;
    const int wid  = tid >> 5;           // 0..15
    const int bi   = blockIdx.x * 128;

    // Phase A: B tile, full K. thread -> n = tid>>3, 8 pairs at (tid&7)*8.
    {
        int n  = tid >> 3;
        int pp = (tid & 7) * 8;
        uint4 h0 = *(const uint4*)&g_W2h[n * 64 + pp];
        uint4 h1 = *(const uint4*)&g_W2h[n * 64 + pp + 4];
        uint4 l0 = *(const uint4*)&g_W2l[n * 64 + pp];
        uint4 l1 = *(const uint4*)&g_W2l[n * 64 + pp + 4];
        *(uint4*)&BsH[n * FSTR + pp]     = h0;
        *(uint4*)&BsH[n * FSTR + pp + 4] = h1;
        *(uint4*)&BsL[n * FSTR + pp]     = l0;
        *(uint4*)&BsL[n * FSTR + pp + 4] = l1;
    }

    // Phase B: aggregate 8 nodes per warp.
    for (int i = 0; i < 8; i++) {
        int w = bi + wid * 8 + i;
        if (w >= N) break;
        int beg = g_off[w];
        int end = beg + g_deg[w];
        float sw = g_dinv[w];

        const uint2 su = *(const uint2*)&g_Hsh[(size_t)w * FHID + lane * 4];
        float2 p0 = __half22float2(*(const __half2*)&su.x);
        float2 p1 = __half22float2(*(const __half2*)&su.y);
        float a0 = p0.x * sw, a1 = p0.y * sw, a2 = p1.x * sw, a3 = p1.y * sw;

        for (int j0 = beg; j0 < end; j0 += 32) {
            int jj = j0 + lane;
            int   myidx = (jj < end) ? g_eidx[jj] : 0;
            float mydv  = (jj < end) ? g_dinv[myidx] : 0.f;
            int m = min(32, end - j0);
            int t = 0;
            for (; t + 4 <= m; t += 4) {
                int   r0 = __shfl_sync(0xffffffffu, myidx, t);
                int   r1 = __shfl_sync(0xffffffffu, myidx, t + 1);
                int   r2 = __shfl_sync(0xffffffffu, myidx, t + 2);
                int   r3 = __shfl_sync(0xffffffffu, myidx, t + 3);
                float d0 = __shfl_sync(0xffffffffu, mydv, t);
                float d1 = __shfl_sync(0xffffffffu, mydv, t + 1);
                float d2 = __shfl_sync(0xffffffffu, mydv, t + 2);
                float d3 = __shfl_sync(0xffffffffu, mydv, t + 3);
                uint2 u0 = *(const uint2*)&g_Hsh[(size_t)r0 * FHID + lane * 4];
                uint2 u1 = *(const uint2*)&g_Hsh[(size_t)r1 * FHID + lane * 4];
                uint2 u2 = *(const uint2*)&g_Hsh[(size_t)r2 * FHID + lane * 4];
                uint2 u3 = *(const uint2*)&g_Hsh[(size_t)r3 * FHID + lane * 4];
                float2 q;
                q = __half22float2(*(const __half2*)&u0.x); a0 = fmaf(q.x, d0, a0); a1 = fmaf(q.y, d0, a1);
                q = __half22float2(*(const __half2*)&u0.y); a2 = fmaf(q.x, d0, a2); a3 = fmaf(q.y, d0, a3);
                q = __half22float2(*(const __half2*)&u1.x); a0 = fmaf(q.x, d1, a0); a1 = fmaf(q.y, d1, a1);
                q = __half22float2(*(const __half2*)&u1.y); a2 = fmaf(q.x, d1, a2); a3 = fmaf(q.y, d1, a3);
                q = __half22float2(*(const __half2*)&u2.x); a0 = fmaf(q.x, d2, a0); a1 = fmaf(q.y, d2, a1);
                q = __half22float2(*(const __half2*)&u2.y); a2 = fmaf(q.x, d2, a2); a3 = fmaf(q.y, d2, a3);
                q = __half22float2(*(const __half2*)&u3.x); a0 = fmaf(q.x, d3, a0); a1 = fmaf(q.y, d3, a1);
                q = __half22float2(*(const __half2*)&u3.y); a2 = fmaf(q.x, d3, a2); a3 = fmaf(q.y, d3, a3);
            }
            for (; t < m; t++) {
                int   r  = __shfl_sync(0xffffffffu, myidx, t);
                float dv = __shfl_sync(0xffffffffu, mydv, t);
                uint2 u = *(const uint2*)&g_Hsh[(size_t)r * FHID + lane * 4];
                float2 q;
                q = __half22float2(*(const __half2*)&u.x); a0 = fmaf(q.x, dv, a0); a1 = fmaf(q.y, dv, a1);
                q = __half22float2(*(const __half2*)&u.y); a2 = fmaf(q.x, dv, a2); a3 = fmaf(q.y, dv, a3);
            }
        }
        float4 bb = ((const float4*)b1)[lane];
        float ox = fmaxf(fmaf(a0, sw, bb.x), 0.f);
        float oy = fmaxf(fmaf(a1, sw, bb.y), 0.f);
        float oz = fmaxf(fmaf(a2, sw, bb.z), 0.f);
        float ow = fmaxf(fmaf(a3, sw, bb.w), 0.f);
        // write H2 row directly into split-bf16 A tiles: row w-bi, pairs 2*lane, 2*lane+1
        uint32_t h0, l0, h1, l1;
        split_pack(ox, oy, h0, l0);
        split_pack(oz, ow, h1, l1);
        int p = (w - bi) * FSTR + 2 * lane;
        AsH[p] = h0; AsH[p + 1] = h1;
        AsL[p] = l0; AsL[p + 1] = l1;
    }
    __syncthreads();

    // Phase C: MMA. 16 warps in 4m x 4n; warp tile 32 rows x 16 cols.
    const int wm = wid & 3;
    const int wn = wid >> 2;
    float acc[2][2][4];
#pragma unroll
    for (int mi = 0; mi < 2; mi++)
#pragma unroll
        for (int ni = 0; ni < 2; ni++)
#pragma unroll
            for (int q = 0; q < 4; q++) acc[mi][ni][q] = 0.f;

#pragma unroll
    for (int ks = 0; ks < 8; ks++) {
        const int pb = ks * 8;
        uint32_t bh[2][2], bl[2][2], afr[2][4];
#pragma unroll
        for (int ni = 0; ni < 2; ni++) {
            int idx = (wn * 16 + ni * 8 + (lane >> 2)) * FSTR + pb + (lane & 3);
            bh[ni][0] = BsH[idx]; bh[ni][1] = BsH[idx + 4];
            bl[ni][0] = BsL[idx]; bl[ni][1] = BsL[idx + 4];
        }
#pragma unroll
        for (int mi = 0; mi < 2; mi++) {
            int rb = wm * 32 + mi * 16 + (lane >> 2);
            int i0 = rb * FSTR + pb + (lane & 3);
            int i1 = i0 + 8 * FSTR;
            afr[mi][0] = AsH[i0]; afr[mi][1] = AsH[i1];
            afr[mi][2] = AsH[i0 + 4]; afr[mi][3] = AsH[i1 + 4];
        }
#pragma unroll
        for (int mi = 0; mi < 2; mi++)
#pragma unroll
            for (int ni = 0; ni < 2; ni++) {
                mma16816(acc[mi][ni], afr[mi], bh[ni]);   // hi*hi
                mma16816(acc[mi][ni], afr[mi], bl[ni]);   // hi*lo
            }
#pragma unroll
        for (int mi = 0; mi < 2; mi++) {
            int rb = wm * 32 + mi * 16 + (lane >> 2);
            int i0 = rb * FSTR + pb + (lane & 3);
            int i1 = i0 + 8 * FSTR;
            afr[mi][0] = AsL[i0]; afr[mi][1] = AsL[i1];
            afr[mi][2] = AsL[i0 + 4]; afr[mi][3] = AsL[i1 + 4];
        }
#pragma unroll
        for (int mi = 0; mi < 2; mi++)
#pragma unroll
            for (int ni = 0; ni < 2; ni++)
                mma16816(acc[mi][ni], afr[mi], bh[ni]);   // lo*hi
    }

    // epilogue: dinv scale, fp16 store
#pragma unroll
    for (int mi = 0; mi < 2; mi++) {
        int r0 = bi + wm * 32 + mi * 16 + (lane >> 2);
        int r1 = r0 + 8;
        float s0 = (r0 < N) ? g_dinv[r0] : 0.f;
        float s1 = (r1 < N) ? g_dinv[r1] : 0.f;
#pragma unroll
        for (int ni = 0; ni < 2; ni++) {
            int c = wn * 16 + ni * 8 + (lane & 3) * 2;
            if (r0 < N) {
                __half2 v = __floats2half2_rn(acc[mi][ni][0] * s0, acc[mi][ni][1] * s0);
                *(__half2*)&g_Hs2h[(size_t)r0 * FOUT + c] = v;
            }
            if (r1 < N) {
                __half2 v = __floats2half2_rn(acc[mi][ni][2] * s1, acc[mi][ni][3] * s1);
                *(__half2*)&g_Hs2h[(size_t)r1 * FOUT + c] = v;
            }
        }
    }
}

// ---------------------------------------------------------------------------
// Agg2 (CSR gather, fp16, MLP=4): one warp per node, lane = half2 (4 B).
// ---------------------------------------------------------------------------
__global__ __launch_bounds__(256) void k_agg2(
    const float* __restrict__ b2, float* __restrict__ out, int N)
{
    int w    = (blockIdx.x * blockDim.x + threadIdx.x) >> 5;
    int lane = threadIdx.x & 31;
    if (w >= N) return;
    int beg = g_off[w];
    int end = beg + g_deg[w];

    float2 acc = __half22float2(*(const __half2*)&g_Hs2h[(size_t)w * FOUT + lane * 2]);

    for (int j0 = beg; j0 < end; j0 += 32) {
        int jj = j0 + lane;
        int myidx = (jj < end) ? g_eidx[jj] : 0;
        int m = min(32, end - j0);
        int t = 0;
        for (; t + 4 <= m; t += 4) {
            int r0 = __shfl_sync(0xffffffffu, myidx, t);
            int r1 = __shfl_sync(0xffffffffu, myidx, t + 1);
            int r2 = __shfl_sync(0xffffffffu, myidx, t + 2);
            int r3 = __shfl_sync(0xffffffffu, myidx, t + 3);
            uint32_t u0 = *(const uint32_t*)&g_Hs2h[(size_t)r0 * FOUT + lane * 2];
            uint32_t u1 = *(const uint32_t*)&g_Hs2h[(size_t)r1 * FOUT + lane * 2];
            uint32_t u2 = *(const uint32_t*)&g_Hs2h[(size_t)r2 * FOUT + lane * 2];
            uint32_t u3 = *(const uint32_t*)&g_Hs2h[(size_t)r3 * FOUT + lane * 2];
            float2 q;
            q = __half22float2(*(const __half2*)&u0); acc.x += q.x; acc.y += q.y;
            q = __half22float2(*(const __half2*)&u1); acc.x += q.x; acc.y += q.y;
            q = __half22float2(*(const __half2*)&u2); acc.x += q.x; acc.y += q.y;
            q = __half22float2(*(const __half2*)&u3); acc.x += q.x; acc.y += q.y;
        }
        for (; t < m; t++) {
            int r = __shfl_sync(0xffffffffu, myidx, t);
            uint32_t u = *(const uint32_t*)&g_Hs2h[(size_t)r * FOUT + lane * 2];
            float2 q = __half22float2(*(const __half2*)&u);
            acc.x += q.x; acc.y += q.y;
        }
    }
    float s = g_dinv[w];
    float2 bb = ((const float2*)b2)[lane];
    float2 o;
    o.x = fmaf(acc.x, s, bb.x);
    o.y = fmaf(acc.y, s, bb.y);
    ((float2*)out)[(size_t)w * 32 + lane] = o;
}

// ---------------------------------------------------------------------------
// Launch: fork gemm1 onto a side stream, overlapping with CSR build.
// ---------------------------------------------------------------------------
extern "C" void kernel_launch(void* const* d_in, const int* in_sizes, int n_in,
                              void* d_out, int out_size)
{
    const float* x  = (const float*)d_in[0];
    const int*   ei = (const int*)  d_in[1];
    const float* W1 = (const float*)d_in[2];
    const float* b1 = (const float*)d_in[3];
    const float* W2 = (const float*)d_in[4];
    const float* b2 = (const float*)d_in[5];
    float* out = (float*)d_out;

    const int N = in_sizes[0] / FIN;     // 100000
    const int E = in_sizes[1] / 2;       // 1600000
    const int* row = ei;
    const int* col = ei + E;

    const int FUSED_SMEM = (2 * 128 * FSTR + 2 * 64 * FSTR) * 4;  // 104448 B
    static bool attr_set = false;
    if (!attr_set) {
        cudaFuncSetAttribute(k_agg1gemm2, cudaFuncAttributeMaxDynamicSharedMemorySize,
                             FUSED_SMEM);
        attr_set = true;
    }

    cudaStream_t s1;
    cudaEvent_t e0, e1;
    cudaStreamCreateWithFlags(&s1, cudaStreamNonBlocking);
    cudaEventCreateWithFlags(&e0, cudaEventDisableTiming);
    cudaEventCreateWithFlags(&e1, cudaEventDisableTiming);

    // Prep (weights + zeroing) on the origin stream.
    k_prep<<<(N + 255) / 256, 256>>>(W1, W2, N);

    // Fork: gemm1 depends only on prep (packed weights) + input X.
    cudaEventRecord(e0, 0);
    cudaStreamWaitEvent(s1, e0, 0);
    k_gemm1<<<(N + 127) / 128, 256, 0, s1>>>(x, N);
    cudaEventRecord(e1, s1);

    // CSR build on the origin stream, concurrent with gemm1.
    k_count<<<(E + 255) / 256, 256>>>(col, E);
    k_scan1<<<(N + 1023) / 1024, 1024>>>(N);
    k_place<<<(E + 255) / 256, 256>>>(row, col, E);

    // Join: fused agg1+gemm2 needs gemm1's Hsh and the CSR.
    cudaStreamWaitEvent(0, e1, 0);
    k_agg1gemm2<<<(N + 127) / 128, 512, FUSED_SMEM>>>(b1, N);

    // Layer 2 aggregation writes d_out directly.
    k_agg2<<<(N * 32 + 255) / 256, 256>>>(b2, out, N);
}

// round 17
// speedup vs baseline: 1.0300x; 1.0300x over previous
#include <cuda_runtime.h>
#include <cuda_bf16.h>
#include <cuda_fp16.h>
#include <cstdint>

// Problem constants (reference: N=100000, E=1600000, IN=HID=128, OUT=64)
#define NMAX 100000
#define FIN  128
#define FHID 128
#define FOUT 64

// ---------------------------------------------------------------------------
// Device-global scratch (no allocation allowed)
// ---------------------------------------------------------------------------
__device__ int      g_deg[NMAX];
__device__ int      g_off[NMAX];               // segment start per node
__device__ int      g_cursor[NMAX];
__device__ int      g_total;                   // single-pass scan base counter
__device__ float    g_dinv[NMAX];
__device__ int      g_eidx[1600000];
__device__ __half   g_Hsh [(size_t)NMAX * FHID]; // X@W1 (UNSCALED), fp16 messages
__device__ float    g_H2  [(size_t)NMAX * FHID]; // relu(dinv*agg1 + b1), fp32
__device__ __half   g_Hs2h[(size_t)NMAX * FOUT]; // (H2@W2)*dinv[row], fp16 messages
// packed split weights: [n][pair] with pair = k/2
__device__ uint32_t g_W1h[128 * 64], g_W1l[128 * 64];
__device__ uint32_t g_W2h[64 * 64],  g_W2l[64 * 64];

// ---------------------------------------------------------------------------
// Helpers
// ---------------------------------------------------------------------------
// Fast bf16 hi/lo split: identical values to the scalar version (RN rounding),
// ~6 SASS per pair instead of ~16. hi packs {f1|f0}, lo packs the residuals.
__device__ __forceinline__ void split_pack(float f0, float f1, uint32_t& hi, uint32_t& lo) {
    asm("cvt.rn.bf16x2.f32 %0, %1, %2;" : "=r"(hi) : "f"(f1), "f"(f0));
    float h0 = __uint_as_float(hi << 16);
    float h1 = __uint_as_float(hi & 0xFFFF0000u);
    asm("cvt.rn.bf16x2.f32 %0, %1, %2;" : "=r"(lo) : "f"(f1 - h1), "f"(f0 - h0));
}

// m16n8k16 bf16 MMA, D += A*B (D==C in-place)
__device__ __forceinline__ void mma16816(float* d, const uint32_t* a, const uint32_t* b) {
    asm volatile(
        "mma.sync.aligned.m16n8k16.row.col.f32.bf16.bf16.f32 "
        "{%0,%1,%2,%3}, {%4,%5,%6,%7}, {%8,%9}, {%0,%1,%2,%3};"
        : "+f"(d[0]), "+f"(d[1]), "+f"(d[2]), "+f"(d[3])
        : "r"(a[0]), "r"(a[1]), "r"(a[2]), "r"(a[3]), "r"(b[0]), "r"(b[1]));
}

#define PSTR 20   // smem row stride in u32: conflict-free fragment access

// ---------------------------------------------------------------------------
// k_prep: zero deg + total, pack W1/W2 into bf16 hi/lo pairs. One kernel.
// ---------------------------------------------------------------------------
__global__ void k_prep(const float* __restrict__ W1, const float* __restrict__ W2, int N) {
    int i = blockIdx.x * blockDim.x + threadIdx.x;
    if (i < N) g_deg[i] = 0;
    if (i == 0) g_total = 0;
    if (i < 128 * 64) {
        int n = i >> 6, p = (i & 63) * 2;
        uint32_t h, l;
        split_pack(W1[(size_t)p * FHID + n], W1[(size_t)(p + 1) * FHID + n], h, l);
        g_W1h[i] = h; g_W1l[i] = l;
    } else if (i < 128 * 64 + 64 * 64) {
        int j = i - 128 * 64;
        int n = j >> 6, p = (j & 63) * 2;
        uint32_t h, l;
        split_pack(W2[(size_t)p * FOUT + n], W2[(size_t)(p + 1) * FOUT + n], h, l);
        g_W2h[j] = h; g_W2l[j] = l;
    }
}

__global__ void k_count(const int* __restrict__ col, int E) {
    int e = blockIdx.x * blockDim.x + threadIdx.x;
    if (e < E) atomicAdd(&g_deg[col[e]], 1);
}

// Single-pass scan: per-block scan + atomic global base.
__global__ __launch_bounds__(1024) void k_scan1(int N) {
    __shared__ int s[1024];
    __shared__ int sbase;
    int t = threadIdx.x;
    int i = blockIdx.x * 1024 + t;
    int v = (i < N) ? g_deg[i] : 0;
    s[t] = v;
    __syncthreads();
#pragma unroll
    for (int d = 1; d < 1024; d <<= 1) {
        int x = s[t];
        if (t >= d) x += s[t - d];
        __syncthreads();
        s[t] = x;
        __syncthreads();
    }
    if (t == 1023) sbase = atomicAdd(&g_total, s[1023]);
    __syncthreads();
    if (i < N) {
        int o = sbase + s[t] - v;
        g_off[i]    = o;
        g_cursor[i] = o;
        g_dinv[i]   = rsqrtf((float)v + 1.0f);
    }
}

__global__ void k_place(const int* __restrict__ row, const int* __restrict__ col, int E) {
    int e = blockIdx.x * blockDim.x + threadIdx.x;
    if (e < E) {
        int c = col[e];
        int p = atomicAdd(&g_cursor[c], 1);
        g_eidx[p] = row[e];
    }
}

// ---------------------------------------------------------------------------
// GEMM1 (mma.sync bf16-split): Hsh = fp16(X @ W1)  -- UNSCALED (no dinv dep).
// CTA 128x128, 8 warps in 2m x 4n. K in 4 chunks of 32. B from packed weights.
// ---------------------------------------------------------------------------
__global__ __launch_bounds__(256) void k_gemm1(
    const float* __restrict__ X, int N)
{
    __shared__ uint32_t AsH[128 * PSTR], AsL[128 * PSTR];
    __shared__ uint32_t BsH[128 * PSTR], BsL[128 * PSTR];

    const int tid  = threadIdx.x;
    const int lane = tid & 31;
    const int wid  = tid >> 5;
    const int wm   = wid & 1;
    const int wn   = wid >> 1;
    const int bi   = blockIdx.x * 128;

    const int ar  = tid >> 1;
    const int akh = (tid & 1) * 16;
    const int arc = min(bi + ar, N - 1);
    const float* Xrow = X + (size_t)arc * FIN;

    const int bn  = tid >> 1;
    const int bp0 = (tid & 1) * 8;

    float acc[4][4][4];
#pragma unroll
    for (int mi = 0; mi < 4; mi++)
#pragma unroll
        for (int ni = 0; ni < 4; ni++)
#pragma unroll
            for (int q = 0; q < 4; q++) acc[mi][ni][q] = 0.f;

    for (int ch = 0; ch < 4; ch++) {
        const int kc = ch * 32;
        const int cp = ch * 16;
        __syncthreads();
#pragma unroll
        for (int i = 0; i < 4; i++) {
            float4 v = *(const float4*)&Xrow[kc + akh + 4 * i];
            uint32_t h0, l0, h1, l1;
            split_pack(v.x, v.y, h0, l0);
            split_pack(v.z, v.w, h1, l1);
            int p = ar * PSTR + (akh >> 1) + 2 * i;
            AsH[p] = h0; AsH[p + 1] = h1;
            AsL[p] = l0; AsL[p + 1] = l1;
        }
        {
            uint4 h0 = *(const uint4*)&g_W1h[bn * 64 + cp + bp0];
            uint4 h1 = *(const uint4*)&g_W1h[bn * 64 + cp + bp0 + 4];
            uint4 l0 = *(const uint4*)&g_W1l[bn * 64 + cp + bp0];
            uint4 l1 = *(const uint4*)&g_W1l[bn * 64 + cp + bp0 + 4];
            *(uint4*)&BsH[bn * PSTR + bp0]     = h0;
            *(uint4*)&BsH[bn * PSTR + bp0 + 4] = h1;
            *(uint4*)&BsL[bn * PSTR + bp0]     = l0;
            *(uint4*)&BsL[bn * PSTR + bp0 + 4] = l1;
        }
        __syncthreads();

#pragma unroll
        for (int ks = 0; ks < 2; ks++) {
            const int pb = ks * 8;
            uint32_t bh[4][2], bl[4][2], afr[4][4];
#pragma unroll
            for (int ni = 0; ni < 4; ni++) {
                int idx = (wn * 32 + ni * 8 + (lane >> 2)) * PSTR + pb + (lane & 3);
                bh[ni][0] = BsH[idx]; bh[ni][1] = BsH[idx + 4];
                bl[ni][0] = BsL[idx]; bl[ni][1] = BsL[idx + 4];
            }
#pragma unroll
            for (int mi = 0; mi < 4; mi++) {
                int rb = wm * 64 + mi * 16 + (lane >> 2);
                int i0 = rb * PSTR + pb + (lane & 3);
                int i1 = i0 + 8 * PSTR;
                afr[mi][0] = AsH[i0]; afr[mi][1] = AsH[i1];
                afr[mi][2] = AsH[i0 + 4]; afr[mi][3] = AsH[i1 + 4];
            }
#pragma unroll
            for (int mi = 0; mi < 4; mi++)
#pragma unroll
                for (int ni = 0; ni < 4; ni++) {
                    mma16816(acc[mi][ni], afr[mi], bh[ni]);   // hi*hi
                    mma16816(acc[mi][ni], afr[mi], bl[ni]);   // hi*lo
                }
#pragma unroll
            for (int mi = 0; mi < 4; mi++) {
                int rb = wm * 64 + mi * 16 + (lane >> 2);
                int i0 = rb * PSTR + pb + (lane & 3);
                int i1 = i0 + 8 * PSTR;
                afr[mi][0] = AsL[i0]; afr[mi][1] = AsL[i1];
                afr[mi][2] = AsL[i0 + 4]; afr[mi][3] = AsL[i1 + 4];
            }
#pragma unroll
            for (int mi = 0; mi < 4; mi++)
#pragma unroll
                for (int ni = 0; ni < 4; ni++)
                    mma16816(acc[mi][ni], afr[mi], bh[ni]);   // lo*hi
        }
    }

    // epilogue: UNSCALED fp16 store
#pragma unroll
    for (int mi = 0; mi < 4; mi++) {
        int r0 = bi + wm * 64 + mi * 16 + (lane >> 2);
        int r1 = r0 + 8;
#pragma unroll
        for (int ni = 0; ni < 4; ni++) {
            int c = wn * 32 + ni * 8 + (lane & 3) * 2;
            if (r0 < N) {
                __half2 v = __floats2half2_rn(acc[mi][ni][0], acc[mi][ni][1]);
                *(__half2*)&g_Hsh[(size_t)r0 * FHID + c] = v;
            }
            if (r1 < N) {
                __half2 v = __floats2half2_rn(acc[mi][ni][2], acc[mi][ni][3]);
                *(__half2*)&g_Hsh[(size_t)r1 * FHID + c] = v;
            }
        }
    }
}

// ---------------------------------------------------------------------------
// Agg1 (CSR gather, fp16, MLP=4): acc = dinv[w]*h[w] + sum dinv[r]*h[r];
// H2 = relu(dinv[w]*acc + b1). dinv shuffled alongside edge index.
// ---------------------------------------------------------------------------
__global__ __launch_bounds__(256) void k_agg1(const float* __restrict__ b1, int N) {
    int w    = (blockIdx.x * blockDim.x + threadIdx.x) >> 5;
    int lane = threadIdx.x & 31;
    if (w >= N) return;
    int beg = g_off[w];
    int end = beg + g_deg[w];
    float sw = g_dinv[w];

    const uint2 su = *(const uint2*)&g_Hsh[(size_t)w * FHID + lane * 4];
    float2 p0 = __half22float2(*(const __half2*)&su.x);
    float2 p1 = __half22float2(*(const __half2*)&su.y);
    float a0 = p0.x * sw, a1 = p0.y * sw, a2 = p1.x * sw, a3 = p1.y * sw;

    for (int j0 = beg; j0 < end; j0 += 32) {
        int jj = j0 + lane;
        int   myidx = (jj < end) ? g_eidx[jj] : 0;
        float mydv  = (jj < end) ? g_dinv[myidx] : 0.f;
        int m = min(32, end - j0);
        int t = 0;
        for (; t + 4 <= m; t += 4) {
            int   r0 = __shfl_sync(0xffffffffu, myidx, t);
            int   r1 = __shfl_sync(0xffffffffu, myidx, t + 1);
            int   r2 = __shfl_sync(0xffffffffu, myidx, t + 2);
            int   r3 = __shfl_sync(0xffffffffu, myidx, t + 3);
            float d0 = __shfl_sync(0xffffffffu, mydv, t);
            float d1 = __shfl_sync(0xffffffffu, mydv, t + 1);
            float d2 = __shfl_sync(0xffffffffu, mydv, t + 2);
            float d3 = __shfl_sync(0xffffffffu, mydv, t + 3);
            uint2 u0 = *(const uint2*)&g_Hsh[(size_t)r0 * FHID + lane * 4];
            uint2 u1 = *(const uint2*)&g_Hsh[(size_t)r1 * FHID + lane * 4];
            uint2 u2 = *(const uint2*)&g_Hsh[(size_t)r2 * FHID + lane * 4];
            uint2 u3 = *(const uint2*)&g_Hsh[(size_t)r3 * FHID + lane * 4];
            float2 q;
            q = __half22float2(*(const __half2*)&u0.x); a0 = fmaf(q.x, d0, a0); a1 = fmaf(q.y, d0, a1);
            q = __half22float2(*(const __half2*)&u0.y); a2 = fmaf(q.x, d0, a2); a3 = fmaf(q.y, d0, a3);
            q = __half22float2(*(const __half2*)&u1.x); a0 = fmaf(q.x, d1, a0); a1 = fmaf(q.y, d1, a1);
            q = __half22float2(*(const __half2*)&u1.y); a2 = fmaf(q.x, d1, a2); a3 = fmaf(q.y, d1, a3);
            q = __half22float2(*(const __half2*)&u2.x); a0 = fmaf(q.x, d2, a0); a1 = fmaf(q.y, d2, a1);
            q = __half22float2(*(const __half2*)&u2.y); a2 = fmaf(q.x, d2, a2); a3 = fmaf(q.y, d2, a3);
            q = __half22float2(*(const __half2*)&u3.x); a0 = fmaf(q.x, d3, a0); a1 = fmaf(q.y, d3, a1);
            q = __half22float2(*(const __half2*)&u3.y); a2 = fmaf(q.x, d3, a2); a3 = fmaf(q.y, d3, a3);
        }
        for (; t < m; t++) {
            int   r  = __shfl_sync(0xffffffffu, myidx, t);
            float dv = __shfl_sync(0xffffffffu, mydv, t);
            uint2 u = *(const uint2*)&g_Hsh[(size_t)r * FHID + lane * 4];
            float2 q;
            q = __half22float2(*(const __half2*)&u.x); a0 = fmaf(q.x, dv, a0); a1 = fmaf(q.y, dv, a1);
            q = __half22float2(*(const __half2*)&u.y); a2 = fmaf(q.x, dv, a2); a3 = fmaf(q.y, dv, a3);
        }
    }
    float4 bb = ((const float4*)b1)[lane];
    float4 o;
    o.x = fmaxf(fmaf(a0, sw, bb.x), 0.f);
    o.y = fmaxf(fmaf(a1, sw, bb.y), 0.f);
    o.z = fmaxf(fmaf(a2, sw, bb.z), 0.f);
    o.w = fmaxf(fmaf(a3, sw, bb.w), 0.f);
    ((float4*)g_H2)[(size_t)w * 32 + lane] = o;
}

// ---------------------------------------------------------------------------
// GEMM2 (mma.sync bf16-split): Hs2h = fp16((H2 @ W2) * dinv[row])
// CTA 128x64, 8 warps in 4m x 2n. K in 4 chunks of 32. B from packed weights.
// ---------------------------------------------------------------------------
__global__ __launch_bounds__(256) void k_gemm2(int N)
{
    __shared__ uint32_t AsH[128 * PSTR], AsL[128 * PSTR];
    __shared__ uint32_t BsH[64 * PSTR], BsL[64 * PSTR];

    const int tid  = threadIdx.x;
    const int lane = tid & 31;
    const int wid  = tid >> 5;
    const int wm   = wid & 3;
    const int wn   = wid >> 2;
    const int bi   = blockIdx.x * 128;

    const int ar  = tid >> 1;
    const int akh = (tid & 1) * 16;
    const int arc = min(bi + ar, N - 1);
    const float* Hrow = g_H2 + (size_t)arc * FHID;

    const int bn  = tid >> 2;
    const int bp0 = (tid & 3) * 4;

    float acc[2][4][4];
#pragma unroll
    for (int mi = 0; mi < 2; mi++)
#pragma unroll
        for (int ni = 0; ni < 4; ni++)
#pragma unroll
            for (int q = 0; q < 4; q++) acc[mi][ni][q] = 0.f;

    for (int ch = 0; ch < 4; ch++) {
        const int kc = ch * 32;
        const int cp = ch * 16;
        __syncthreads();
#pragma unroll
        for (int i = 0; i < 4; i++) {
            float4 v = *(const float4*)&Hrow[kc + akh + 4 * i];
            uint32_t h0, l0, h1, l1;
            split_pack(v.x, v.y, h0, l0);
            split_pack(v.z, v.w, h1, l1);
            int p = ar * PSTR + (akh >> 1) + 2 * i;
            AsH[p] = h0; AsH[p + 1] = h1;
            AsL[p] = l0; AsL[p + 1] = l1;
        }
        {
            uint4 h = *(const uint4*)&g_W2h[bn * 64 + cp + bp0];
            uint4 l = *(const uint4*)&g_W2l[bn * 64 + cp + bp0];
            *(uint4*)&BsH[bn * PSTR + bp0] = h;
            *(uint4*)&BsL[bn * PSTR + bp0] = l;
        }
        __syncthreads();

#pragma unroll
        for (int ks = 0; ks < 2; ks++) {
            const int pb = ks * 8;
            uint32_t bh[4][2], bl[4][2], afr[2][4];
#pragma unroll
            for (int ni = 0; ni < 4; ni++) {
                int idx = (wn * 32 + ni * 8 + (lane >> 2)) * PSTR + pb + (lane & 3);
                bh[ni][0] = BsH[idx]; bh[ni][1] = BsH[idx + 4];
                bl[ni][0] = BsL[idx]; bl[ni][1] = BsL[idx + 4];
            }
#pragma unroll
            for (int mi = 0; mi < 2; mi++) {
                int rb = wm * 32 + mi * 16 + (lane >> 2);
                int i0 = rb * PSTR + pb + (lane & 3);
                int i1 = i0 + 8 * PSTR;
                afr[mi][0] = AsH[i0]; afr[mi][1] = AsH[i1];
                afr[mi][2] = AsH[i0 + 4]; afr[mi][3] = AsH[i1 + 4];
            }
#pragma unroll
            for (int mi = 0; mi < 2; mi++)
#pragma unroll
                for (int ni = 0; ni < 4; ni++) {
                    mma16816(acc[mi][ni], afr[mi], bh[ni]);
                    mma16816(acc[mi][ni], afr[mi], bl[ni]);
                }
#pragma unroll
            for (int mi = 0; mi < 2; mi++) {
                int rb = wm * 32 + mi * 16 + (lane >> 2);
                int i0 = rb * PSTR + pb + (lane & 3);
                int i1 = i0 + 8 * PSTR;
                afr[mi][0] = AsL[i0]; afr[mi][1] = AsL[i1];
                afr[mi][2] = AsL[i0 + 4]; afr[mi][3] = AsL[i1 + 4];
            }
#pragma unroll
            for (int mi = 0; mi < 2; mi++)
#pragma unroll
                for (int ni = 0; ni < 4; ni++)
                    mma16816(acc[mi][ni], afr[mi], bh[ni]);
        }
    }

#pragma unroll
    for (int mi = 0; mi < 2; mi++) {
        int r0 = bi + wm * 32 + mi * 16 + (lane >> 2);
        int r1 = r0 + 8;
        float s0 = (r0 < N) ? g_dinv[r0] : 0.f;
        float s1 = (r1 < N) ? g_dinv[r1] : 0.f;
#pragma unroll
        for (int ni = 0; ni < 4; ni++) {
            int c = wn * 32 + ni * 8 + (lane & 3) * 2;
            if (r0 < N) {
                __half2 v = __floats2half2_rn(acc[mi][ni][0] * s0, acc[mi][ni][1] * s0);
                *(__half2*)&g_Hs2h[(size_t)r0 * FOUT + c] = v;
            }
            if (r1 < N) {
                __half2 v = __floats2half2_rn(acc[mi][ni][2] * s1, acc[mi][ni][3] * s1);
                *(__half2*)&g_Hs2h[(size_t)r1 * FOUT + c] = v;
            }
        }
    }
}

// ---------------------------------------------------------------------------
// Agg2 (CSR gather, fp16, MLP=4): one warp per node, lane = half2 (4 B).
// ---------------------------------------------------------------------------
__global__ __launch_bounds__(256) void k_agg2(
    const float* __restrict__ b2, float* __restrict__ out, int N)
{
    int w    = (blockIdx.x * blockDim.x + threadIdx.x) >> 5;
    int lane = threadIdx.x & 31;
    if (w >= N) return;
    int beg = g_off[w];
    int end = beg + g_deg[w];

    float2 acc = __half22float2(*(const __half2*)&g_Hs2h[(size_t)w * FOUT + lane * 2]);

    for (int j0 = beg; j0 < end; j0 += 32) {
        int jj = j0 + lane;
        int myidx = (jj < end) ? g_eidx[jj] : 0;
        int m = min(32, end - j0);
        int t = 0;
        for (; t + 4 <= m; t += 4) {
            int r0 = __shfl_sync(0xffffffffu, myidx, t);
            int r1 = __shfl_sync(0xffffffffu, myidx, t + 1);
            int r2 = __shfl_sync(0xffffffffu, myidx, t + 2);
            int r3 = __shfl_sync(0xffffffffu, myidx, t + 3);
            uint32_t u0 = *(const uint32_t*)&g_Hs2h[(size_t)r0 * FOUT + lane * 2];
            uint32_t u1 = *(const uint32_t*)&g_Hs2h[(size_t)r1 * FOUT + lane * 2];
            uint32_t u2 = *(const uint32_t*)&g_Hs2h[(size_t)r2 * FOUT + lane * 2];
            uint32_t u3 = *(const uint32_t*)&g_Hs2h[(size_t)r3 * FOUT + lane * 2];
            float2 q;
            q = __half22float2(*(const __half2*)&u0); acc.x += q.x; acc.y += q.y;
            q = __half22float2(*(const __half2*)&u1); acc.x += q.x; acc.y += q.y;
            q = __half22float2(*(const __half2*)&u2); acc.x += q.x; acc.y += q.y;
            q = __half22float2(*(const __half2*)&u3); acc.x += q.x; acc.y += q.y;
        }
        for (; t < m; t++) {
            int r = __shfl_sync(0xffffffffu, myidx, t);
            uint32_t u = *(const uint32_t*)&g_Hs2h[(size_t)r * FOUT + lane * 2];
            float2 q = __half22float2(*(const __half2*)&u);
            acc.x += q.x; acc.y += q.y;
        }
    }
    float s = g_dinv[w];
    float2 bb = ((const float2*)b2)[lane];
    float2 o;
    o.x = fmaf(acc.x, s, bb.x);
    o.y = fmaf(acc.y, s, bb.y);
    ((float2*)out)[(size_t)w * 32 + lane] = o;
}

// ---------------------------------------------------------------------------
// Launch: fork gemm1 onto a side stream, overlapping with CSR build.
// ---------------------------------------------------------------------------
extern "C" void kernel_launch(void* const* d_in, const int* in_sizes, int n_in,
                              void* d_out, int out_size)
{
    const float* x  = (const float*)d_in[0];
    const int*   ei = (const int*)  d_in[1];
    const float* W1 = (const float*)d_in[2];
    const float* b1 = (const float*)d_in[3];
    const float* W2 = (const float*)d_in[4];
    const float* b2 = (const float*)d_in[5];
    float* out = (float*)d_out;

    const int N = in_sizes[0] / FIN;     // 100000
    const int E = in_sizes[1] / 2;       // 1600000
    const int* row = ei;
    const int* col = ei + E;

    // Host-side stream/event objects (not device memory). Created per call;
    // intentionally not destroyed (kernel_launch runs only a handful of times).
    cudaStream_t s1;
    cudaEvent_t e0, e1;
    cudaStreamCreateWithFlags(&s1, cudaStreamNonBlocking);
    cudaEventCreateWithFlags(&e0, cudaEventDisableTiming);
    cudaEventCreateWithFlags(&e1, cudaEventDisableTiming);

    // Prep (weights + zeroing) on the origin stream.
    k_prep<<<(N + 255) / 256, 256>>>(W1, W2, N);

    // Fork: gemm1 depends only on prep (packed weights) + input X.
    cudaEventRecord(e0, 0);
    cudaStreamWaitEvent(s1, e0, 0);
    k_gemm1<<<(N + 127) / 128, 256, 0, s1>>>(x, N);
    cudaEventRecord(e1, s1);

    // CSR build on the origin stream, concurrent with gemm1.
    k_count<<<(E + 255) / 256, 256>>>(col, E);
    k_scan1<<<(N + 1023) / 1024, 1024>>>(N);
    k_place<<<(E + 255) / 256, 256>>>(row, col, E);

    // Join: agg1 needs both gemm1 and the CSR.
    cudaStreamWaitEvent(0, e1, 0);
    k_agg1<<<(N * 32 + 255) / 256, 256>>>(b1, N);

    // Layer 2 (serial).
    k_gemm2<<<(N + 127) / 128, 256>>>(N);
    k_agg2<<<(N * 32 + 255) / 256, 256>>>(b2, out, N);
}